// round 1
// baseline (speedup 1.0000x reference)
#include <cuda_runtime.h>
#include <cstdint>

// Problem shape (fixed by the dataset)
#define BSZ 32
#define TLEN 4096
#define CDIM 256
#define NPB (TLEN * CDIM)        // 1048576 elements per batch
#define NBINS 4096               // 12-bit bucket: (bits of fabs(x)) >> 19
#define CAP 131072               // candidate buffer capacity per batch

// ---------------- device scratch (static, allocation-free) ----------------
__device__ float    g_distrust[BSZ];
__device__ unsigned g_hist[BSZ][NBINS];
__device__ unsigned g_count[BSZ];
__device__ unsigned g_below[BSZ];
__device__ unsigned g_lo_bits[BSZ];
__device__ unsigned g_hi_bits[BSZ];
__device__ unsigned g_k0[BSZ];
__device__ unsigned g_k1[BSZ];
__device__ float    g_frac[BSZ];
__device__ float    g_thresh[BSZ];
__device__ unsigned g_buf[BSZ][CAP];

// ---------------- K0: zero scratch (graph replays need this) ----------------
__global__ void k0_zero() {
    unsigned i = blockIdx.x * blockDim.x + threadIdx.x;
    unsigned n = BSZ * NBINS;
    unsigned stride = gridDim.x * blockDim.x;
    unsigned* h = &g_hist[0][0];
    for (unsigned j = i; j < n; j += stride) h[j] = 0u;
    if (i < BSZ) {
        g_distrust[i] = 0.f;
        g_count[i] = 0u;
        g_below[i] = 0u;
    }
}

// ---------------- K1: distrust stats + subsampled histogram ----------------
// Grid: 1024 blocks x 256 threads. Block handles 128 rows (one batch each).
__global__ void __launch_bounds__(256) k1_stats(
    const float* __restrict__ s, const float* __restrict__ t,
    const float* __restrict__ risk)
{
    __shared__ unsigned sh_hist[NBINS];
    __shared__ float sh_wsum[8];
    const int tid  = threadIdx.x;
    const int warp = tid >> 5;
    const int lane = tid & 31;

    for (int i = tid; i < NBINS; i += 256) sh_hist[i] = 0u;
    __syncthreads();

    const int row0 = blockIdx.x * 128;
    const int b = row0 / TLEN;
    const float rc = risk[b];

    float acc = 0.f;
#pragma unroll 4
    for (int it = 0; it < 16; ++it) {
        const int row = row0 + warp * 16 + it;
        const size_t base = (size_t)row * CDIM + lane * 8;
        float4 s0 = *(const float4*)(s + base);
        float4 s1 = *(const float4*)(s + base + 4);
        float4 t0 = *(const float4*)(t + base);
        float4 t1 = *(const float4*)(t + base + 4);

        // subsample: 8 of 256 elements per row -> 1/32 rate, 32768/batch
        if ((lane & 3) == 0) {
            unsigned bits = __float_as_uint(fabsf(s0.x));
            atomicAdd(&sh_hist[bits >> 19], 1u);
        }

        float d0 = s0.x - t0.x, d1 = s0.y - t0.y, d2 = s0.z - t0.z, d3 = s0.w - t0.w;
        float d4 = s1.x - t1.x, d5 = s1.y - t1.y, d6 = s1.z - t1.z, d7 = s1.w - t1.w;
        float r = d0*d0 + d1*d1 + d2*d2 + d3*d3 + d4*d4 + d5*d5 + d6*d6 + d7*d7;
#pragma unroll
        for (int o = 16; o; o >>= 1) r += __shfl_xor_sync(0xffffffffu, r, o);
        if (lane == 0) {
            float delta = r * (1.f / CDIM);
            float u = fminf(fmaxf(delta * 2.f, 0.f), 1.f);
            acc += fmaxf(u, rc * u);
        }
    }
    if (lane == 0) sh_wsum[warp] = acc;
    __syncthreads();
    if (tid == 0) {
        float ssum = 0.f;
        for (int w = 0; w < 8; ++w) ssum += sh_wsum[w];
        atomicAdd(&g_distrust[b], ssum);
    }
    for (int i = tid; i < NBINS; i += 256) {
        unsigned v = sh_hist[i];
        if (v) atomicAdd(&g_hist[b][i], v);
    }
}

// ---------------- K2: pick ranks + conservative candidate bucket range ------
__global__ void k2_buckets() {
    int b = threadIdx.x;
    if (b >= BSZ) return;
    float db = g_distrust[b] * (1.f / TLEN);
    const float pr = (float)(0.99 - 0.9);
    float p = 0.99f - pr * db;

    double pos = (double)p * (double)(NPB - 1);
    unsigned k0 = (unsigned)pos;                 // floor (pos >= 0)
    if (k0 > NPB - 1) k0 = NPB - 1;
    double frac = pos - (double)k0;
    unsigned k1 = (k0 + 1 <= NPB - 1) ? k0 + 1 : NPB - 1;

    const unsigned S = TLEN * 8;                 // exact sample count per batch
    double scale = (double)S / (double)NPB;
    long rs0 = (long)((double)k0 * scale) - 400; // ~7 sigma margin in sample units
    long rs1 = (long)((double)k1 * scale) + 400;
    if (rs0 < 0) rs0 = 0;
    if (rs1 > (long)S - 1) rs1 = (long)S - 1;

    unsigned cum = 0;
    int lob = -1, hib = -1;
    for (int i = 0; i < NBINS; ++i) {
        cum += g_hist[b][i];
        if (lob < 0 && (long)cum > rs0) lob = i;
        if (hib < 0 && (long)cum > rs1) { hib = i; break; }
    }
    if (lob < 0) lob = NBINS - 1;
    if (hib < 0) hib = NBINS - 1;

    g_lo_bits[b] = ((unsigned)lob) << 19;
    g_hi_bits[b] = ((unsigned)(hib + 1)) << 19;  // exclusive upper bound
    g_k0[b] = k0;
    g_k1[b] = k1;
    g_frac[b] = (float)frac;
}

// ---------------- K3: exact below-count + candidate compaction --------------
__global__ void __launch_bounds__(256) k3_compact(const float* __restrict__ s) {
    const float4* s4 = (const float4*)s;
    const unsigned total4 = (unsigned)BSZ * (NPB / 4);   // 8388608
    const unsigned stride = gridDim.x * blockDim.x;
    const int lane = threadIdx.x & 31;

    for (unsigned i = blockIdx.x * blockDim.x + threadIdx.x; i < total4; i += stride) {
        const int b = i >> 18;                           // NPB/4 = 2^18
        const unsigned lo = g_lo_bits[b];
        const unsigned hi = g_hi_bits[b];
        float4 v = s4[i];
        unsigned bv[4];
        bv[0] = __float_as_uint(fabsf(v.x));
        bv[1] = __float_as_uint(fabsf(v.y));
        bv[2] = __float_as_uint(fabsf(v.z));
        bv[3] = __float_as_uint(fabsf(v.w));

        int nb = 0;
#pragma unroll
        for (int j = 0; j < 4; ++j) nb += (bv[j] < lo);
        int tot = nb;
#pragma unroll
        for (int o = 16; o; o >>= 1) tot += __shfl_xor_sync(0xffffffffu, tot, o);
        if (lane == 0 && tot) atomicAdd(&g_below[b], (unsigned)tot);

#pragma unroll
        for (int j = 0; j < 4; ++j) {
            bool pred = (bv[j] >= lo) && (bv[j] < hi);
            unsigned msk = __ballot_sync(0xffffffffu, pred);
            if (msk) {
                unsigned cnt = __popc(msk);
                unsigned base = 0;
                if (lane == 0) base = atomicAdd(&g_count[b], cnt);
                base = __shfl_sync(0xffffffffu, base, 0);
                if (pred) {
                    unsigned off = base + __popc(msk & ((1u << lane) - 1u));
                    if (off < CAP) g_buf[b][off] = bv[j];
                }
            }
        }
    }
}

// ---------------- K4: exact radix-select on candidates ----------------------
__device__ unsigned block_select(const unsigned* __restrict__ buf, unsigned m, unsigned r) {
    __shared__ unsigned sh_hist[256];
    __shared__ unsigned sh_byte, sh_r;
    unsigned prefix = 0, known = 0;
    for (int shift = 24; shift >= 0; shift -= 8) {
        for (int i = threadIdx.x; i < 256; i += blockDim.x) sh_hist[i] = 0u;
        __syncthreads();
        for (unsigned i = threadIdx.x; i < m; i += blockDim.x) {
            unsigned v = buf[i];
            if ((v & known) == prefix)
                atomicAdd(&sh_hist[(v >> shift) & 255u], 1u);
        }
        __syncthreads();
        if (threadIdx.x == 0) {
            unsigned cum = 0, byte = 255, rr = r;
            for (unsigned bb = 0; bb < 256; ++bb) {
                unsigned c = sh_hist[bb];
                if (cum + c > r) { byte = bb; rr = r - cum; break; }
                cum += c;
            }
            sh_byte = byte;
            sh_r = rr;
        }
        __syncthreads();
        prefix |= sh_byte << shift;
        known  |= 0xFFu << shift;
        r = sh_r;
        __syncthreads();
    }
    return prefix;
}

__global__ void __launch_bounds__(256) k4_select() {
    const int b = blockIdx.x;
    unsigned m = g_count[b];
    if (m > CAP) m = CAP;
    if (m == 0) { if (threadIdx.x == 0) g_thresh[b] = 0.f; return; }
    const unsigned below = g_below[b];
    unsigned r0 = g_k0[b] - below;
    unsigned r1 = g_k1[b] - below;
    if (r0 >= m) r0 = m - 1;   // safety clamp (should not trigger)
    if (r1 >= m) r1 = m - 1;
    unsigned v0 = block_select(g_buf[b], m, r0);
    unsigned v1 = block_select(g_buf[b], m, r1);
    if (threadIdx.x == 0) {
        float f0 = __uint_as_float(v0);
        float f1 = __uint_as_float(v1);
        g_thresh[b] = f0 + (f1 - f0) * g_frac[b];
    }
}

// ---------------- K5: clip stream -------------------------------------------
__global__ void __launch_bounds__(256) k5_clip(const float* __restrict__ s,
                                               float* __restrict__ out)
{
    const float4* s4 = (const float4*)s;
    float4* o4 = (float4*)out;
    const unsigned total4 = (unsigned)BSZ * (NPB / 4);
    const unsigned stride = gridDim.x * blockDim.x;
    for (unsigned i = blockIdx.x * blockDim.x + threadIdx.x; i < total4; i += stride) {
        const int b = i >> 18;
        const float th = g_thresh[b];
        float4 v = s4[i];
        v.x = fminf(fmaxf(v.x, -th), th);
        v.y = fminf(fmaxf(v.y, -th), th);
        v.z = fminf(fmaxf(v.z, -th), th);
        v.w = fminf(fmaxf(v.w, -th), th);
        o4[i] = v;
    }
}

// ---------------- launch -----------------------------------------------------
extern "C" void kernel_launch(void* const* d_in, const int* in_sizes, int n_in,
                              void* d_out, int out_size)
{
    const float* s    = (const float*)d_in[0];
    const float* t    = (const float*)d_in[1];
    const float* risk = (const float*)d_in[2];
    float* out = (float*)d_out;

    k0_zero<<<128, 256>>>();
    k1_stats<<<1024, 256>>>(s, t, risk);
    k2_buckets<<<1, 32>>>();
    k3_compact<<<4096, 256>>>(s);
    k4_select<<<BSZ, 256>>>();
    k5_clip<<<8192, 256>>>(s, out);
}

// round 2
// speedup vs baseline: 3.6109x; 3.6109x over previous
#include <cuda_runtime.h>
#include <cstdint>

// Problem shape (fixed by the dataset)
#define BSZ 32
#define TLEN 4096
#define CDIM 256
#define NPB (TLEN * CDIM)        // 1048576 elements per batch
#define NBINS 4096               // 12-bit bucket: (bits of fabs(x)) >> 19
#define CAP 131072               // candidate buffer capacity per batch
#define PAD 64                   // 64 uints = 256B stride -> distinct L2 lines

// ---------------- device scratch (static, allocation-free) ----------------
__device__ float    g_distrust[BSZ][PAD];
__device__ unsigned g_hist[BSZ][NBINS];
__device__ unsigned g_count[BSZ][PAD];
__device__ unsigned g_below[BSZ][PAD];
__device__ unsigned g_lo_bits[BSZ];
__device__ unsigned g_hi_bits[BSZ];
__device__ unsigned g_k0[BSZ];
__device__ unsigned g_k1[BSZ];
__device__ float    g_frac[BSZ];
__device__ float    g_thresh[BSZ];
__device__ unsigned g_buf[BSZ][CAP];

// ---------------- K0: zero scratch (graph replays need this) ----------------
__global__ void k0_zero() {
    unsigned i = blockIdx.x * blockDim.x + threadIdx.x;
    unsigned n = BSZ * NBINS;
    unsigned stride = gridDim.x * blockDim.x;
    unsigned* h = &g_hist[0][0];
    for (unsigned j = i; j < n; j += stride) h[j] = 0u;
    if (i < BSZ) {
        g_distrust[i][0] = 0.f;
        g_count[i][0] = 0u;
        g_below[i][0] = 0u;
    }
}

// ---------------- K1: distrust stats + subsampled histogram ----------------
// Grid: 1024 blocks x 256 threads. Block handles 128 rows (one batch each).
__global__ void __launch_bounds__(256) k1_stats(
    const float* __restrict__ s, const float* __restrict__ t,
    const float* __restrict__ risk)
{
    __shared__ unsigned sh_hist[NBINS];
    __shared__ float sh_wsum[8];
    const int tid  = threadIdx.x;
    const int warp = tid >> 5;
    const int lane = tid & 31;

    for (int i = tid; i < NBINS; i += 256) sh_hist[i] = 0u;
    __syncthreads();

    const int row0 = blockIdx.x * 128;
    const int b = row0 / TLEN;
    const float rc = risk[b];

    float acc = 0.f;
#pragma unroll 4
    for (int it = 0; it < 16; ++it) {
        const int row = row0 + warp * 16 + it;
        const size_t base = (size_t)row * CDIM + lane * 8;
        float4 s0 = *(const float4*)(s + base);
        float4 s1 = *(const float4*)(s + base + 4);
        float4 t0 = *(const float4*)(t + base);
        float4 t1 = *(const float4*)(t + base + 4);

        // subsample: 8 of 256 elements per row -> 1/32 rate, 32768/batch
        if ((lane & 3) == 0) {
            unsigned bits = __float_as_uint(fabsf(s0.x));
            atomicAdd(&sh_hist[bits >> 19], 1u);
        }

        float d0 = s0.x - t0.x, d1 = s0.y - t0.y, d2 = s0.z - t0.z, d3 = s0.w - t0.w;
        float d4 = s1.x - t1.x, d5 = s1.y - t1.y, d6 = s1.z - t1.z, d7 = s1.w - t1.w;
        float r = d0*d0 + d1*d1 + d2*d2 + d3*d3 + d4*d4 + d5*d5 + d6*d6 + d7*d7;
#pragma unroll
        for (int o = 16; o; o >>= 1) r += __shfl_xor_sync(0xffffffffu, r, o);
        if (lane == 0) {
            float delta = r * (1.f / CDIM);
            float u = fminf(fmaxf(delta * 2.f, 0.f), 1.f);
            acc += fmaxf(u, rc * u);
        }
    }
    if (lane == 0) sh_wsum[warp] = acc;
    __syncthreads();
    if (tid == 0) {
        float ssum = 0.f;
        for (int w = 0; w < 8; ++w) ssum += sh_wsum[w];
        atomicAdd(&g_distrust[b][0], ssum);
    }
    for (int i = tid; i < NBINS; i += 256) {
        unsigned v = sh_hist[i];
        if (v) atomicAdd(&g_hist[b][i], v);
    }
}

// ---------------- K2: pick ranks + conservative candidate bucket range ------
// 32 blocks (one per batch) x 256 threads; two-level smem scan of 4096 bins.
__global__ void __launch_bounds__(256) k2_buckets() {
    const int b = blockIdx.x;
    const int tid = threadIdx.x;
    __shared__ unsigned seg[256];
    __shared__ int sh_lob, sh_hib;
    __shared__ unsigned sh_rs0, sh_rs1;

    if (tid == 0) { sh_lob = NBINS; sh_hib = NBINS; }

    // load my 16 bins, segment sum
    unsigned local[16];
    unsigned ssum = 0;
#pragma unroll
    for (int j = 0; j < 16; ++j) {
        local[j] = g_hist[b][tid * 16 + j];
        ssum += local[j];
    }
    seg[tid] = ssum;
    __syncthreads();

    // exclusive scan of segment sums (serial by thread 0; 256 smem adds, cheap)
    if (tid == 0) {
        unsigned run = 0;
        for (int i = 0; i < 256; ++i) { unsigned v = seg[i]; seg[i] = run; run += v; }

        // compute ranks + sample-rank targets
        float db = g_distrust[b][0] * (1.f / TLEN);
        float p = 0.99f - 0.09f * db;
        double pos = (double)p * (double)(NPB - 1);
        unsigned k0 = (unsigned)pos;
        if (k0 > NPB - 1) k0 = NPB - 1;
        double frac = pos - (double)k0;
        unsigned k1 = (k0 + 1 <= NPB - 1) ? k0 + 1 : NPB - 1;
        g_k0[b] = k0;
        g_k1[b] = k1;
        g_frac[b] = (float)frac;

        const unsigned S = TLEN * 8;               // samples per batch
        double scale = (double)S / (double)NPB;
        long rs0 = (long)((double)k0 * scale) - 400;   // ~7 sigma margin
        long rs1 = (long)((double)k1 * scale) + 400;
        if (rs0 < 0) rs0 = 0;
        if (rs1 > (long)S - 1) rs1 = (long)S - 1;
        sh_rs0 = (unsigned)rs0;
        sh_rs1 = (unsigned)rs1;
    }
    __syncthreads();

    // each thread searches its 16-bin range for the crossings
    const unsigned rs0 = sh_rs0, rs1 = sh_rs1;
    unsigned cum = seg[tid];
    int lob = NBINS, hib = NBINS;
#pragma unroll
    for (int j = 0; j < 16; ++j) {
        cum += local[j];
        if (lob == NBINS && cum > rs0) lob = tid * 16 + j;
        if (hib == NBINS && cum > rs1) hib = tid * 16 + j;
    }
    if (lob < NBINS) atomicMin(&sh_lob, lob);
    if (hib < NBINS) atomicMin(&sh_hib, hib);
    __syncthreads();

    if (tid == 0) {
        int lo = (sh_lob < NBINS) ? sh_lob : NBINS - 1;
        int hi = (sh_hib < NBINS) ? sh_hib : NBINS - 1;
        g_lo_bits[b] = ((unsigned)lo) << 19;
        g_hi_bits[b] = ((unsigned)(hi + 1)) << 19;   // exclusive upper bound
    }
}

// ---------------- K3: exact below-count + candidate compaction --------------
// One block = one contiguous 8192-element chunk of ONE batch.
// 4096 blocks total (128 per batch). Candidates staged in smem (cannot
// overflow: <= 8192 per block), then one global atomic reserves the range.
__global__ void __launch_bounds__(256) k3_compact(const float* __restrict__ s) {
    __shared__ unsigned sh_buf[8192];
    __shared__ unsigned sh_cnt, sh_base;
    __shared__ int sh_below[8];

    const int tid  = threadIdx.x;
    const int warp = tid >> 5;
    const int lane = tid & 31;
    const int b     = blockIdx.x >> 7;       // 128 blocks per batch
    const int chunk = blockIdx.x & 127;

    if (tid == 0) sh_cnt = 0;
    __syncthreads();

    const unsigned lo = g_lo_bits[b];
    const unsigned hi = g_hi_bits[b];
    const float4* s4 = (const float4*)s + (size_t)b * (NPB / 4) + (size_t)chunk * 2048;

    int below = 0;
#pragma unroll
    for (int it = 0; it < 8; ++it) {
        float4 v = s4[it * 256 + tid];
        unsigned bv[4];
        bv[0] = __float_as_uint(fabsf(v.x));
        bv[1] = __float_as_uint(fabsf(v.y));
        bv[2] = __float_as_uint(fabsf(v.z));
        bv[3] = __float_as_uint(fabsf(v.w));
#pragma unroll
        for (int j = 0; j < 4; ++j) {
            below += (bv[j] < lo);
            bool pred = (bv[j] >= lo) && (bv[j] < hi);
            unsigned msk = __ballot_sync(0xffffffffu, pred);
            if (msk) {
                unsigned cnt = __popc(msk);
                unsigned base = 0;
                if (lane == 0) base = atomicAdd(&sh_cnt, cnt);
                base = __shfl_sync(0xffffffffu, base, 0);
                if (pred)
                    sh_buf[base + __popc(msk & ((1u << lane) - 1u))] = bv[j];
            }
        }
    }

    // block-reduce below-count -> single global atomic
#pragma unroll
    for (int o = 16; o; o >>= 1) below += __shfl_xor_sync(0xffffffffu, below, o);
    if (lane == 0) sh_below[warp] = below;
    __syncthreads();
    if (tid == 0) {
        int tot = 0;
        for (int w = 0; w < 8; ++w) tot += sh_below[w];
        if (tot) atomicAdd(&g_below[b][0], (unsigned)tot);
        sh_base = atomicAdd(&g_count[b][0], sh_cnt);
    }
    __syncthreads();

    // coalesced copy-out of staged candidates
    const unsigned cnt = sh_cnt, gbase = sh_base;
    for (unsigned i = tid; i < cnt; i += 256) {
        unsigned off = gbase + i;
        if (off < CAP) g_buf[b][off] = sh_buf[i];
    }
}

// ---------------- K4: exact radix-select on candidates ----------------------
__device__ unsigned block_select(const unsigned* __restrict__ buf, unsigned m, unsigned r) {
    __shared__ unsigned sh_hist[256];
    __shared__ unsigned sh_byte, sh_r;
    unsigned prefix = 0, known = 0;
    for (int shift = 24; shift >= 0; shift -= 8) {
        for (int i = threadIdx.x; i < 256; i += blockDim.x) sh_hist[i] = 0u;
        __syncthreads();
        for (unsigned i = threadIdx.x; i < m; i += blockDim.x) {
            unsigned v = buf[i];
            if ((v & known) == prefix)
                atomicAdd(&sh_hist[(v >> shift) & 255u], 1u);
        }
        __syncthreads();
        if (threadIdx.x == 0) {
            unsigned cum = 0, byte = 255, rr = r;
            for (unsigned bb = 0; bb < 256; ++bb) {
                unsigned c = sh_hist[bb];
                if (cum + c > r) { byte = bb; rr = r - cum; break; }
                cum += c;
            }
            sh_byte = byte;
            sh_r = rr;
        }
        __syncthreads();
        prefix |= sh_byte << shift;
        known  |= 0xFFu << shift;
        r = sh_r;
        __syncthreads();
    }
    return prefix;
}

__global__ void __launch_bounds__(256) k4_select() {
    const int b = blockIdx.x;
    unsigned m = g_count[b][0];
    if (m > CAP) m = CAP;
    if (m == 0) { if (threadIdx.x == 0) g_thresh[b] = 0.f; return; }
    const long below = (long)g_below[b][0];
    long r0 = (long)g_k0[b] - below;
    long r1 = (long)g_k1[b] - below;
    if (r0 < 0) r0 = 0;
    if (r1 < 0) r1 = 0;
    if (r0 >= (long)m) r0 = m - 1;   // safety clamp (should not trigger)
    if (r1 >= (long)m) r1 = m - 1;
    unsigned v0 = block_select(g_buf[b], m, (unsigned)r0);
    unsigned v1 = block_select(g_buf[b], m, (unsigned)r1);
    if (threadIdx.x == 0) {
        float f0 = __uint_as_float(v0);
        float f1 = __uint_as_float(v1);
        g_thresh[b] = f0 + (f1 - f0) * g_frac[b];
    }
}

// ---------------- K5: clip stream -------------------------------------------
__global__ void __launch_bounds__(256) k5_clip(const float* __restrict__ s,
                                               float* __restrict__ out)
{
    const float4* s4 = (const float4*)s;
    float4* o4 = (float4*)out;
    const unsigned total4 = (unsigned)BSZ * (NPB / 4);
    const unsigned stride = gridDim.x * blockDim.x;
    for (unsigned i = blockIdx.x * blockDim.x + threadIdx.x; i < total4; i += stride) {
        const int b = i >> 18;
        const float th = g_thresh[b];
        float4 v = s4[i];
        v.x = fminf(fmaxf(v.x, -th), th);
        v.y = fminf(fmaxf(v.y, -th), th);
        v.z = fminf(fmaxf(v.z, -th), th);
        v.w = fminf(fmaxf(v.w, -th), th);
        o4[i] = v;
    }
}

// ---------------- launch -----------------------------------------------------
extern "C" void kernel_launch(void* const* d_in, const int* in_sizes, int n_in,
                              void* d_out, int out_size)
{
    const float* s    = (const float*)d_in[0];
    const float* t    = (const float*)d_in[1];
    const float* risk = (const float*)d_in[2];
    float* out = (float*)d_out;

    k0_zero<<<512, 256>>>();
    k1_stats<<<1024, 256>>>(s, t, risk);
    k2_buckets<<<BSZ, 256>>>();
    k3_compact<<<4096, 256>>>(s);
    k4_select<<<BSZ, 256>>>();
    k5_clip<<<8192, 256>>>(s, out);
}